// round 15
// baseline (speedup 1.0000x reference)
#include <cuda_runtime.h>
#include <cuda_bf16.h>

// Problem dims (fixed by the reference)
#define BB 16
#define TT 512     // text tokens
#define AA 4096    // audio frames
#define DD 256     // hidden dim
#define GUARD 48   // numerator truncation radius: exp(-48^2/100) ~ 1e-10
#define WIN 32     // denominator token window
#define CH 256     // frames per chunk
#define NCH (AA / CH)  // 16 chunks per batch

// -(1/TEMP^2) * log2(e):  exp(-d^2/100) == exp2(d^2 * KNEG)
#define KNEG (-0.014426950408889634f)

// 3-slot token-weight partials (slot = owning chunk relative to token's
// primary chunk). Every element written exactly once per launch.
__device__ float g_Wp[3 * BB * TT];

__device__ __forceinline__ float ex2a(float x) {
    float y; asm("ex2.approx.ftz.f32 %0, %1;" : "=f"(y) : "f"(x)); return y;
}
__device__ __forceinline__ float rcpa(float x) {
    float y; asm("rcp.approx.ftz.f32 %0, %1;" : "=f"(y) : "f"(x)); return y;
}

// M1: fused denominators + numerator scatter, one block per (b, frame chunk).
// Grid: BB * NCH = 256 blocks x 256 threads.
__global__ __launch_bounds__(256) void fused_weights_kernel(
    const float* __restrict__ centers)   // [B, T] (sorted per b)
{
    const int b   = blockIdx.x >> 4;
    const int C   = blockIdx.x & 15;
    const int tid = threadIdx.x;
    const int a0  = C * CH;

    __shared__ float sc[TT];
    __shared__ float sinv[CH];
    __shared__ int   anch[17];
    __shared__ int   tb[4];   // token boundaries of chunks C-1, C, C+1, C+2

    for (int i = tid; i < TT; i += 256) sc[i] = centers[b * TT + i];
    __syncthreads();

    // anchors: first center >= a0 + 16*i  (17 searches, stride-16 frames)
    if (tid < 17) {
        const float tgt = (float)(a0 + tid * 16);
        int lo = 0, hi = TT;
#pragma unroll
        for (int it = 0; it < 9; it++) {
            const int mid = (lo + hi) >> 1;
            if (sc[mid] < tgt) lo = mid + 1; else hi = mid;
        }
        anch[tid] = lo;
    }
    // token-range boundaries: first center >= 256*(C-1+j), j=0..3
    if (tid >= 32 && tid < 36) {
        const float tgt = (float)(CH * (C - 1 + (tid - 32)));
        int lo = 0, hi = TT;
#pragma unroll
        for (int it = 0; it < 9; it++) {
            const int mid = (lo + hi) >> 1;
            if (sc[mid] < tgt) lo = mid + 1; else hi = mid;
        }
        tb[tid - 32] = lo;
    }
    __syncthreads();

    // ---------- Phase A: denominators for owned frames ----------
    {
        const float ts = (float)(a0 + tid);
        int j = anch[tid >> 4];
        const int jend = anch[(tid >> 4) + 1];
        while (j < jend && sc[j] < ts) j++;
        const int j0 = min(max(j - WIN / 2, 0), TT - WIN);

        float s0 = 0.f, s1 = 0.f, s2 = 0.f, s3 = 0.f;
#pragma unroll
        for (int k = 0; k < WIN; k += 4) {
            const float d0 = sc[j0 + k + 0] - ts;
            const float d1 = sc[j0 + k + 1] - ts;
            const float d2 = sc[j0 + k + 2] - ts;
            const float d3 = sc[j0 + k + 3] - ts;
            s0 += ex2a((KNEG * d0) * d0);
            s1 += ex2a((KNEG * d1) * d1);
            s2 += ex2a((KNEG * d2) * d2);
            s3 += ex2a((KNEG * d3) * d3);
        }
        sinv[tid] = rcpa((s0 + s1) + (s2 + s3));
    }
    __syncthreads();

    // ---------- Phase B: numerators over owned frames ----------
    const int t0 = tb[0], t1 = tb[1], t2 = tb[2], t3 = tb[3];
    const int q  = tid & 3;               // quad member: frames lo+q, step 4
    const int NT = t3 - t0;
    const int trips = (NT + 63) >> 6;     // 64 tokens per trip (256 thr / 4)

    for (int k = 0; k < trips; k++) {
        const int i = t0 + (tid >> 2) + (k << 6);
        float acc = 0.0f;
        if (i < t3) {
            const float c = sc[i];
            const int alo = max(0, (int)c - GUARD);
            const int ahi = min(AA, (int)c + GUARD + 1);
            const int lo  = max(alo, a0);
            const int hi  = min(ahi, a0 + CH);
            for (int a = lo + q; a < hi; a += 4) {
                const float d = (float)a - c;
                acc = fmaf(ex2a((KNEG * d) * d), sinv[a - a0], acc);
            }
        }
        acc += __shfl_xor_sync(0xffffffffu, acc, 1);
        acc += __shfl_xor_sync(0xffffffffu, acc, 2);
        if (q == 0 && i < t3) {
            // primary chunk p: [t0,t1)->C-1, [t1,t2)->C, [t2,t3)->C+1
            const int p = (i < t1) ? (C - 1) : ((i < t2) ? C : (C + 1));
            const int s = C - p + 1;                   // 2, 1, 0
            g_Wp[(s * BB + b) * TT + i] = acc;
        }
    }

    // Boundary zero-fill: slot 0 of p=0 tokens, slot 2 of p=15 tokens.
    if (C == 0)
        for (int i = t1 + tid; i < t2; i += 256)
            g_Wp[(0 * BB + b) * TT + i] = 0.0f;
    if (C == NCH - 1)
        for (int i = t1 + tid; i < t2; i += 256)
            g_Wp[(2 * BB + b) * TT + i] = 0.0f;

    // All g_Wp writes issued: allow the dependent kernel's blocks to launch.
    asm volatile("griddepcontrol.launch_dependents;" ::: "memory");
}

// M2: out[b,d] = sum_t hidden[b,d,t] * W[b,t], W = sum of 3 slots.
// PDL: prefetch the hidden stream BEFORE griddepcontrol.wait (independent of
// M1), then read g_Wp after the wait.
// Grid: 512 blocks x 256 threads; warp-per-row, float4 loads.
__global__ __launch_bounds__(256) void weighted_reduce_kernel(
    const float* __restrict__ hidden,  // [B, D, T]
    float* __restrict__ out)           // [B, D]
{
    const int b    = blockIdx.x >> 5;   // 32 blocks per batch
    const int dblk = blockIdx.x & 31;   // 8 d per block (warp per d)
    const int tid  = threadIdx.x;
    const int lane = tid & 31;
    const int warp = tid >> 5;

    // ---- Prefetch hidden (input tensor; no dependency on M1) ----
    const int d = dblk * 8 + warp;
    const float4* h4 = (const float4*)(hidden + ((size_t)(b * DD + d)) * TT);
    float4 h[4];
#pragma unroll
    for (int k = 0; k < 4; k++) h[k] = __ldg(h4 + lane + 32 * k);

    // ---- Wait for M1's g_Wp to be visible ----
    asm volatile("griddepcontrol.wait;" ::: "memory");

    __shared__ float4 w4[TT / 4];
    if (tid < TT / 4) {
        float4 v = make_float4(0.f, 0.f, 0.f, 0.f);
#pragma unroll
        for (int s = 0; s < 3; s++) {
            const float4 p = ((const float4*)(g_Wp + (s * BB + b) * TT))[tid];
            v.x += p.x; v.y += p.y; v.z += p.z; v.w += p.w;
        }
        w4[tid] = v;
    }
    __syncthreads();

    float s = 0.0f;
#pragma unroll
    for (int k = 0; k < 4; k++) {
        const float4 w = w4[lane + 32 * k];
        s = fmaf(h[k].x, w.x, fmaf(h[k].y, w.y, fmaf(h[k].z, w.z, fmaf(h[k].w, w.w, s))));
    }
#pragma unroll
    for (int o = 16; o >= 1; o >>= 1)
        s += __shfl_xor_sync(0xffffffffu, s, o);

    if (lane == 0) out[b * DD + d] = s;
}

extern "C" void kernel_launch(void* const* d_in, const int* in_sizes, int n_in,
                              void* d_out, int out_size) {
    const float* hidden   = (const float*)d_in[0];  // [B, D, T] f32
    const float* centers  = (const float*)d_in[1];  // [B, T]    f32
    float* out = (float*)d_out;                     // [B, D]    f32

    (void)in_sizes; (void)n_in; (void)out_size;

    fused_weights_kernel<<<BB * NCH, 256>>>(centers);

    // Launch M2 with programmatic dependent launch so its prelude overlaps
    // M1's tail. Without PDL support the wait is a no-op and stream order
    // still guarantees correctness.
    cudaLaunchConfig_t cfg = {};
    cfg.gridDim  = dim3(BB * 32, 1, 1);
    cfg.blockDim = dim3(256, 1, 1);
    cudaLaunchAttribute attrs[1];
    attrs[0].id = cudaLaunchAttributeProgrammaticStreamSerialization;
    attrs[0].val.programmaticStreamSerializationAllowed = 1;
    cfg.attrs = attrs;
    cfg.numAttrs = 1;
    cudaLaunchKernelEx(&cfg, weighted_reduce_kernel, hidden, out);
}